// round 12
// baseline (speedup 1.0000x reference)
#include <cuda_runtime.h>
#include <math.h>

#define NN 50000
#define EE 800000
#define NF 512
#define NH 128
#define NC 16
#define NEG 0.2f
#define FEPS 1e-9f
#define NBLK ((NN + 255) / 256)

// ---------------- scratch layout (floats) ----------------
// zeroed-every-launch region:
#define OUTW1_OFF ((size_t)0)
#define OUTW2_OFF (OUTW1_OFF + NN)
#define CUR_OFF   (OUTW2_OFF + NN)         // int cursors
#define DEG_OFF   (CUR_OFF + NN)           // int in-degree
#define LOSS_OFF  (DEG_OFF + NN)
#define ZERO_TOTAL (LOSS_OFF + 1)
// non-zeroed region:
#define HLATP_OFF  (((ZERO_TOTAL + 3)/4)*4)
#define HLATP2_OFF (HLATP_OFF + (size_t)NN*NC)
#define H1_OFF     (HLATP2_OFF + (size_t)NN*NC)
#define H2_OFF     (H1_OFF + (size_t)NN*NH)
#define RST1_OFF   (H2_OFF + (size_t)NN*NC)
#define EL1_OFF    (RST1_OFF + (size_t)NN*NH)
#define ER1_OFF    (EL1_OFF + NN)
#define EL2_OFF    (ER1_OFF + NN)
#define ER2_OFF    (EL2_OFF + NN)
#define EW_OFF     (ER2_OFF + NN)          // edge weights in CSR order
#define RP_OFF     (EW_OFF + EE)           // int row_ptr[NN+1]
#define CSRC_OFF   (((RP_OFF + NN + 1 + 3)/4)*4)  // int csr_src[EE]
#define CDST_OFF   (CSRC_OFF + EE)         // int csr_dst[EE]
#define EORIG_OFF  (CDST_OFF + EE)         // int csr slot -> orig edge id
#define SC_OFF     (EORIG_OFF + EE)
#define PART_OFF   (SC_OFF + 16)
#define TOTALF     (PART_OFF + NBLK + 16)

__device__ __align__(256) float g_s[TOTALF];

__device__ __forceinline__ float elu1(float x){ return x > 0.f ? x : expf(x) - 1.f; }

// packed f32x2 helpers (sm_100+ PTX; SASS FFMA2 — 2 lane-FMAs per issue)
__device__ __forceinline__ unsigned long long splat2(float a){
    unsigned long long r;
    asm("mov.b64 %0, {%1, %1};" : "=l"(r) : "f"(a));
    return r;
}
__device__ __forceinline__ void fma2(unsigned long long& d, unsigned long long a,
                                     unsigned long long b){
    asm("fma.rn.f32x2 %0, %1, %2, %0;" : "+l"(d) : "l"(a), "l"(b));
}
__device__ __forceinline__ float2 unpack2(unsigned long long v){
    float lo, hi;
    asm("mov.b64 {%0, %1}, %2;" : "=f"(lo), "=f"(hi) : "l"(v));
    return make_float2(lo, hi);
}

// ---------------- zero + scalars ----------------
__global__ void k_zero(const float* b1, const float* a1, const float* t1,
                       const float* b2, const float* a2, const float* t2){
    if (blockIdx.x == 0 && threadIdx.x == 0){
        float* sc = g_s + SC_OFF;
        sc[0] = 2.0f / (expf(-b1[0]) + 1.0f);
        float e0 = expf(a1[0]), e1 = expf(a1[1]);
        sc[1] = e0 / (e0 + e1); sc[2] = e1 / (e0 + e1);
        sc[3] = FEPS / (expf(-t1[0]) + 1.0f);
        sc[4] = 2.0f / (expf(-b2[0]) + 1.0f);
        float f0 = expf(a2[0]), f1 = expf(a2[1]);
        sc[5] = f0 / (f0 + f1); sc[6] = f1 / (f0 + f1);
        sc[7] = FEPS / (expf(-t2[0]) + 1.0f);
    }
    size_t i = (size_t)blockIdx.x * blockDim.x + threadIdx.x;
    size_t stride = (size_t)gridDim.x * blockDim.x;
    for (; i < ZERO_TOTAL; i += stride) g_s[i] = 0.f;
}

__global__ void k_indeg(const int* __restrict__ dst){
    int e = blockIdx.x * blockDim.x + threadIdx.x;
    if (e < EE) atomicAdd((int*)(g_s + DEG_OFF) + dst[e], 1);
}

// ---------------- multi-block scan ----------------
__global__ void k_scanA(){
    __shared__ int wsum[8];
    int lane = threadIdx.x & 31, wid = threadIdx.x >> 5;
    int i = blockIdx.x * 256 + threadIdx.x;
    int v = (i < NN) ? ((const int*)(g_s + DEG_OFF))[i] : 0;
    int x = v;
#pragma unroll
    for (int o = 1; o < 32; o <<= 1){
        int t = __shfl_up_sync(0xffffffffu, x, o);
        if (lane >= o) x += t;
    }
    if (lane == 31) wsum[wid] = x;
    __syncthreads();
    if (threadIdx.x < 8){
        int y = wsum[threadIdx.x];
#pragma unroll
        for (int o = 1; o < 8; o <<= 1){
            int t = __shfl_up_sync(0xffu, y, o);
            if (threadIdx.x >= o) y += t;
        }
        wsum[threadIdx.x] = y;
    }
    __syncthreads();
    int incl = x + (wid ? wsum[wid - 1] : 0);
    if (i < NN) ((int*)(g_s + RP_OFF))[i + 1] = incl;
    if (threadIdx.x == 255) ((int*)(g_s + PART_OFF))[blockIdx.x] = incl;
}

__global__ void k_scanB(){
    __shared__ int off_s;
    if (threadIdx.x == 0) off_s = 0;
    __syncthreads();
    const int* part = (const int*)(g_s + PART_OFF);
    int p = 0;
    for (int j = threadIdx.x; j < blockIdx.x; j += 256) p += part[j];
#pragma unroll
    for (int o = 16; o; o >>= 1) p += __shfl_xor_sync(0xffffffffu, p, o);
    if ((threadIdx.x & 31) == 0 && p) atomicAdd(&off_s, p);
    __syncthreads();
    int i = blockIdx.x * 256 + threadIdx.x;
    if (i < NN) ((int*)(g_s + RP_OFF))[i + 1] += off_s;
    if (blockIdx.x == 0 && threadIdx.x == 0) ((int*)(g_s + RP_OFF))[0] = 0;
}

__global__ void k_scatter(const int* __restrict__ src, const int* __restrict__ dst){
    int e = blockIdx.x * blockDim.x + threadIdx.x;
    if (e >= EE) return;
    int d = dst[e];
    int* cur = (int*)(g_s + CUR_OFF);
    const int* rp = (const int*)(g_s + RP_OFF);
    int p = rp[d] + atomicAdd(&cur[d], 1);
    ((int*)(g_s + CSRC_OFF))[p] = src[e];
    ((int*)(g_s + CDST_OFF))[p] = d;
    ((int*)(g_s + EORIG_OFF))[p] = e;
}

// ---------------- fused double 16x16 dense ----------------
__global__ void k_dense2x(const float* __restrict__ latp,
                          const float* __restrict__ W1, const float* __restrict__ B1,
                          const float* __restrict__ W2, const float* __restrict__ B2){
    __shared__ float W1s[256], W2s[256], bb1[16], bb2[16];
    int t = threadIdx.x;
    W1s[t] = W1[t]; W2s[t] = W2[t];
    if (t < 16){ bb1[t] = B1[t]; bb2[t] = B2[t]; }
    __syncthreads();
    int idx = blockIdx.x * blockDim.x + t;
    if (idx >= NN * NC) return;
    int c = idx & 15;
    float in = latp[idx];
    float acc = bb1[c];
#pragma unroll
    for (int k = 0; k < 16; k++){
        float ik = __shfl_sync(0xffffffffu, in, k, 16);
        acc = fmaf(ik, W1s[k * 16 + c], acc);
    }
    float h = elu1(acc);
    g_s[HLATP_OFF + idx] = h;
    float acc2 = bb2[c];
#pragma unroll
    for (int k = 0; k < 16; k++){
        float hk = __shfl_sync(0xffffffffu, h, k, 16);
        acc2 = fmaf(hk, W2s[k * 16 + c], acc2);
    }
    g_s[HLATP2_OFF + idx] = elu1(acc2);
}

// ---------------- GEMM1: f32x2 FMA + register-prefetch pipeline ----------------
__global__ __launch_bounds__(256, 2) void k_gemm1(const float* __restrict__ A,
                                                  const float* __restrict__ B,
                                                  const float* __restrict__ wu,
                                                  const float* __restrict__ wv){
    __shared__ float As[32][132];
    __shared__ float Bs[32][128];
    int tid = threadIdx.x;
    int m0 = blockIdx.x * 128;
    int tx = tid & 15, ty = tid >> 4;
    unsigned long long accp[8][4];
#pragma unroll
    for (int i = 0; i < 8; i++)
#pragma unroll
        for (int p = 0; p < 4; p++) accp[i][p] = 0ull;

    float4 pa[4], pb[4];
    // prefetch tile 0
#pragma unroll
    for (int l = 0; l < 4; l++){
        int id = tid + l * 256;
        int row = id >> 3, kc = (id & 7) * 4;
        int gm = m0 + row; if (gm >= NN) gm = NN - 1;
        pa[l] = *(const float4*)(A + (size_t)gm * NF + kc);
        int brow = id >> 5, c = (id & 31) * 4;
        pb[l] = *(const float4*)(B + (size_t)brow * NH + c);
    }

    for (int t = 0; t < NF / 32; t++){
        __syncthreads();   // prior tile's compute done before overwriting smem
#pragma unroll
        for (int l = 0; l < 4; l++){
            int id = tid + l * 256;
            int row = id >> 3, kc = (id & 7) * 4;
            As[kc + 0][row] = pa[l].x; As[kc + 1][row] = pa[l].y;
            As[kc + 2][row] = pa[l].z; As[kc + 3][row] = pa[l].w;
            int brow = id >> 5, c = (id & 31) * 4;
            *(float4*)&Bs[brow][c] = pb[l];
        }
        __syncthreads();
        if (t + 1 < NF / 32){
            int k0 = (t + 1) * 32;
#pragma unroll
            for (int l = 0; l < 4; l++){
                int id = tid + l * 256;
                int row = id >> 3, kc = (id & 7) * 4;
                int gm = m0 + row; if (gm >= NN) gm = NN - 1;
                pa[l] = *(const float4*)(A + (size_t)gm * NF + k0 + kc);
                int brow = id >> 5, c = (id & 31) * 4;
                pb[l] = *(const float4*)(B + (size_t)(k0 + brow) * NH + c);
            }
        }
#pragma unroll
        for (int kk = 0; kk < 32; kk++){
            float a[8];
            *(float4*)(a)     = *(float4*)&As[kk][ty * 8];
            *(float4*)(a + 4) = *(float4*)&As[kk][ty * 8 + 4];
            unsigned long long b2[4];
            b2[0] = *(const unsigned long long*)&Bs[kk][tx * 8];
            b2[1] = *(const unsigned long long*)&Bs[kk][tx * 8 + 2];
            b2[2] = *(const unsigned long long*)&Bs[kk][tx * 8 + 4];
            b2[3] = *(const unsigned long long*)&Bs[kk][tx * 8 + 6];
#pragma unroll
            for (int i = 0; i < 8; i++){
                unsigned long long ap = splat2(a[i]);
                fma2(accp[i][0], ap, b2[0]);
                fma2(accp[i][1], ap, b2[1]);
                fma2(accp[i][2], ap, b2[2]);
                fma2(accp[i][3], ap, b2[3]);
            }
        }
    }
    float wuv[8], wvv[8];
    *(float4*)(wuv)     = ((const float4*)wu)[tx * 2];
    *(float4*)(wuv + 4) = ((const float4*)wu)[tx * 2 + 1];
    *(float4*)(wvv)     = ((const float4*)wv)[tx * 2];
    *(float4*)(wvv + 4) = ((const float4*)wv)[tx * 2 + 1];
#pragma unroll
    for (int i = 0; i < 8; i++){
        int gm = m0 + ty * 8 + i;
        float acc[8];
#pragma unroll
        for (int p = 0; p < 4; p++){
            float2 u = unpack2(accp[i][p]);
            acc[2 * p] = u.x; acc[2 * p + 1] = u.y;
        }
        float ep = 0.f, vp = 0.f;
#pragma unroll
        for (int j = 0; j < 8; j++){
            float cv = acc[j];
            float l = cv > 0.f ? cv : NEG * cv;
            ep = fmaf(l, wuv[j], ep);
            vp = fmaf(l, wvv[j], vp);
        }
#pragma unroll
        for (int o = 1; o < 16; o <<= 1){
            ep += __shfl_xor_sync(0xffffffffu, ep, o);
            vp += __shfl_xor_sync(0xffffffffu, vp, o);
        }
        if (gm < NN){
            float* c = g_s + H1_OFF + (size_t)gm * NH + tx * 8;
            *(float4*)c       = make_float4(acc[0], acc[1], acc[2], acc[3]);
            *(float4*)(c + 4) = make_float4(acc[4], acc[5], acc[6], acc[7]);
            if (tx == 0){ g_s[EL1_OFF + gm] = ep; g_s[ER1_OFF + gm] = vp; }
        }
    }
}

// ---------------- edge pass 1: 8 lanes per edge, CSR slot order ----------------
__global__ void k_edge1(const float* __restrict__ ws){
    int t = blockIdx.x * blockDim.x + threadIdx.x;
    int j = t >> 3, l = t & 7;
    if (j >= EE) return;
    int s = ((const int*)(g_s + CSRC_OFF))[j];
    int d = ((const int*)(g_s + CDST_OFF))[j];
    const float4* hs = (const float4*)(g_s + H1_OFF + (size_t)s * NH);
    const float4* hd = (const float4*)(g_s + H1_OFF + (size_t)d * NH);
    float sdf = 0.f;
#pragma unroll
    for (int q = 0; q < 4; q++){
        float4 a = hs[l + 8 * q];
        float4 b = hd[l + 8 * q];
        float v;
        v = a.x - b.x; sdf = fmaf(v, v, sdf);
        v = a.y - b.y; sdf = fmaf(v, v, sdf);
        v = a.z - b.z; sdf = fmaf(v, v, sdf);
        v = a.w - b.w; sdf = fmaf(v, v, sdf);
    }
    float2 fs = *(const float2*)(g_s + HLATP_OFF + (size_t)s * NC + l * 2);
    float2 fd = *(const float2*)(g_s + HLATP_OFF + (size_t)d * NC + l * 2);
    float2 w2 = *(const float2*)(ws + l * 2);
    float q0 = fs.x - fd.x, q1 = fs.y - fd.y;
    float sds = q0 * q0 + q1 * q1;
    float st = fs.x * w2.x * fd.x + fs.y * w2.y * fd.y;
#pragma unroll
    for (int o = 4; o; o >>= 1){
        sdf += __shfl_xor_sync(0xffffffffu, sdf, o);
        sds += __shfl_xor_sync(0xffffffffu, sds, o);
        st  += __shfl_xor_sync(0xffffffffu, st,  o);
    }
    if (l == 0){
        const float* sc = g_s + SC_OFF;
        float ev = g_s[EL1_OFF + s] + g_s[ER1_OFF + d] + st;
        float dd = sc[1] * sdf + sc[2] * sds;
        float ew = expf(ev - sc[0] * dd) + FEPS;
        g_s[EW_OFF + j] = ew;
        atomicAdd(&g_s[OUTW1_OFF + s], ew);
    }
}

// ---------------- CSR aggregation layer1 (inw computed in-warp) ----------------
__global__ void k_agg1(){
    int d = (blockIdx.x * blockDim.x + threadIdx.x) >> 5;
    int lane = threadIdx.x & 31;
    if (d >= NN) return;
    const int* rp = (const int*)(g_s + RP_OFF);
    const int* cs = (const int*)(g_s + CSRC_OFF);
    const float* ewc = g_s + EW_OFF;
    int b = rp[d], eend = rp[d + 1];
    float s_ew = 0.f;
    for (int j = b + lane; j < eend; j += 32) s_ew += ewc[j];
#pragma unroll
    for (int o = 16; o; o >>= 1) s_ew += __shfl_xor_sync(0xffffffffu, s_ew, o);
    float inw_r = rsqrtf(s_ew);
    float4 A = make_float4(0.f, 0.f, 0.f, 0.f);
    float4 Bc = make_float4(0.f, 0.f, 0.f, 0.f);
    int j = b;
    for (; j + 3 < eend; j += 4){
        int s0 = cs[j], s1 = cs[j + 1], s2 = cs[j + 2], s3 = cs[j + 3];
        float a0 = inw_r * rsqrtf(g_s[OUTW1_OFF + s0]) * ewc[j];
        float a1 = inw_r * rsqrtf(g_s[OUTW1_OFF + s1]) * ewc[j + 1];
        float a2 = inw_r * rsqrtf(g_s[OUTW1_OFF + s2]) * ewc[j + 2];
        float a3 = inw_r * rsqrtf(g_s[OUTW1_OFF + s3]) * ewc[j + 3];
        float4 h0 = ((const float4*)(g_s + H1_OFF + (size_t)s0 * NH))[lane];
        float4 h1 = ((const float4*)(g_s + H1_OFF + (size_t)s1 * NH))[lane];
        float4 h2 = ((const float4*)(g_s + H1_OFF + (size_t)s2 * NH))[lane];
        float4 h3 = ((const float4*)(g_s + H1_OFF + (size_t)s3 * NH))[lane];
        A.x = fmaf(h0.x, a0, A.x); A.y = fmaf(h0.y, a0, A.y);
        A.z = fmaf(h0.z, a0, A.z); A.w = fmaf(h0.w, a0, A.w);
        Bc.x = fmaf(h1.x, a1, Bc.x); Bc.y = fmaf(h1.y, a1, Bc.y);
        Bc.z = fmaf(h1.z, a1, Bc.z); Bc.w = fmaf(h1.w, a1, Bc.w);
        A.x = fmaf(h2.x, a2, A.x); A.y = fmaf(h2.y, a2, A.y);
        A.z = fmaf(h2.z, a2, A.z); A.w = fmaf(h2.w, a2, A.w);
        Bc.x = fmaf(h3.x, a3, Bc.x); Bc.y = fmaf(h3.y, a3, Bc.y);
        Bc.z = fmaf(h3.z, a3, Bc.z); Bc.w = fmaf(h3.w, a3, Bc.w);
    }
    for (; j < eend; j++){
        int s0 = cs[j];
        float a0 = inw_r * rsqrtf(g_s[OUTW1_OFF + s0]) * ewc[j];
        float4 h0 = ((const float4*)(g_s + H1_OFF + (size_t)s0 * NH))[lane];
        A.x = fmaf(h0.x, a0, A.x); A.y = fmaf(h0.y, a0, A.y);
        A.z = fmaf(h0.z, a0, A.z); A.w = fmaf(h0.w, a0, A.w);
    }
    float perm = g_s[SC_OFF + 3] / ((float)(eend - b) + FEPS);
    float4 hd = ((const float4*)(g_s + H1_OFF + (size_t)d * NH))[lane];
    float4 r;
    r.x = elu1(A.x + Bc.x + hd.x * perm);
    r.y = elu1(A.y + Bc.y + hd.y * perm);
    r.z = elu1(A.z + Bc.z + hd.z * perm);
    r.w = elu1(A.w + Bc.w + hd.w * perm);
    ((float4*)(g_s + RST1_OFF + (size_t)d * NH))[lane] = r;
}

// ---------------- GEMM2 (smem-tiled) + fused el2/er2 ----------------
__global__ __launch_bounds__(256) void k_gemm2n(const float* __restrict__ W,
                                                const float* __restrict__ wu,
                                                const float* __restrict__ wv){
    __shared__ float Ws[NH * NC];
    __shared__ float Rs[16][NH];
    int tid = threadIdx.x;
    for (int i = tid; i < NH * NC; i += 256) Ws[i] = W[i];
    int nb = blockIdx.x * 16;
#pragma unroll
    for (int it = 0; it < 8; it++){
        int i = tid + it * 256;
        int row = i >> 7, col = i & 127;
        Rs[row][col] = g_s[RST1_OFF + (size_t)(nb + row) * NH + col];
    }
    __syncthreads();
    int nl = tid >> 4, c = tid & 15;
    float acc = 0.f;
#pragma unroll
    for (int k = 0; k < NH; k++) acc = fmaf(Rs[nl][k], Ws[k * 16 + c], acc);
    int n = nb + nl;
    g_s[H2_OFF + (size_t)n * NC + c] = acc;
    float l = acc > 0.f ? acc : NEG * acc;
    float up = l * wu[c], vp = l * wv[c];
#pragma unroll
    for (int o = 8; o; o >>= 1){
        up += __shfl_xor_sync(0xffffffffu, up, o);
        vp += __shfl_xor_sync(0xffffffffu, vp, o);
    }
    if (c == 0){ g_s[EL2_OFF + n] = up; g_s[ER2_OFF + n] = vp; }
}

// ---------------- edge pass 2 (+ loss fused), CSR slot order ----------------
__global__ void k_edge2(const float* __restrict__ ws, const float* __restrict__ lw){
    int j = blockIdx.x * blockDim.x + threadIdx.x;
    float lacc = 0.f;
    if (j < EE){
        int s = ((const int*)(g_s + CSRC_OFF))[j];
        int d = ((const int*)(g_s + CDST_OFF))[j];
        const float4* hs = (const float4*)(g_s + H2_OFF + (size_t)s * NC);
        const float4* hd = (const float4*)(g_s + H2_OFF + (size_t)d * NC);
        const float4* fs = (const float4*)(g_s + HLATP2_OFF + (size_t)s * NC);
        const float4* fd = (const float4*)(g_s + HLATP2_OFF + (size_t)d * NC);
        const float4* w4 = (const float4*)ws;
        float sdf = 0.f, sds = 0.f, st = 0.f, pdot = 0.f;
#pragma unroll
        for (int q = 0; q < 4; q++){
            float4 a = hs[q], b = hd[q];
            float v;
            v = a.x - b.x; sdf += v * v;
            v = a.y - b.y; sdf += v * v;
            v = a.z - b.z; sdf += v * v;
            v = a.w - b.w; sdf += v * v;
            float4 p = fs[q], r = fd[q], w = w4[q];
            v = p.x - r.x; sds += v * v;
            v = p.y - r.y; sds += v * v;
            v = p.z - r.z; sds += v * v;
            v = p.w - r.w; sds += v * v;
            st += p.x * w.x * r.x + p.y * w.y * r.y + p.z * w.z * r.z + p.w * w.w * r.w;
            pdot += p.x * r.x + p.y * r.y + p.z * r.z + p.w * r.w;
        }
        const float* sc = g_s + SC_OFF;
        float ev = g_s[EL2_OFF + s] + g_s[ER2_OFF + d] + st;
        float ew = expf(ev - sc[4] * (sc[5] * sdf + sc[6] * sds)) + FEPS;
        g_s[EW_OFF + j] = ew;
        atomicAdd(&g_s[OUTW2_OFF + s], ew);
        lacc = lw[((const int*)(g_s + EORIG_OFF))[j]] * pdot;
    }
#pragma unroll
    for (int o = 16; o; o >>= 1) lacc += __shfl_xor_sync(0xffffffffu, lacc, o);
    if ((threadIdx.x & 31) == 0) atomicAdd(&g_s[LOSS_OFF], lacc);
}

// ---------------- CSR aggregation layer2 + final log-softmax ----------------
__global__ void k_agg2_final(float* __restrict__ out, int out_size){
    int d = (blockIdx.x * blockDim.x + threadIdx.x) >> 5;
    int lane = threadIdx.x & 31;
    if (d >= NN) return;
    if (d == 0 && lane == 0 && out_size > NN * NC) out[NN * NC] = g_s[LOSS_OFF];
    const int* rp = (const int*)(g_s + RP_OFF);
    const int* cs = (const int*)(g_s + CSRC_OFF);
    const float* ewc = g_s + EW_OFF;
    int b = rp[d], eend = rp[d + 1];
    int c = lane & 15;
    int half = lane >> 4;
    float s_ew = 0.f;
    for (int j = b + lane; j < eend; j += 32) s_ew += ewc[j];
#pragma unroll
    for (int o = 16; o; o >>= 1) s_ew += __shfl_xor_sync(0xffffffffu, s_ew, o);
    float inw_r = rsqrtf(s_ew);
    float acc = 0.f;
    for (int j = b + half; j < eend; j += 2){
        int s = cs[j];
        float a = inw_r * rsqrtf(g_s[OUTW2_OFF + s]) * ewc[j];
        acc = fmaf(g_s[H2_OFF + (size_t)s * NC + c], a, acc);
    }
    acc += __shfl_xor_sync(0xffffffffu, acc, 16);
    float perm = g_s[SC_OFF + 7] / ((float)(eend - b) + FEPS);
    float t = elu1(acc + g_s[H2_OFF + (size_t)d * NC + c] * perm);
    float mx = t;
#pragma unroll
    for (int o = 8; o; o >>= 1) mx = fmaxf(mx, __shfl_xor_sync(0xffffffffu, mx, o));
    float s2 = expf(t - mx);
#pragma unroll
    for (int o = 8; o; o >>= 1) s2 += __shfl_xor_sync(0xffffffffu, s2, o);
    float lse = mx + logf(s2);
    if (lane < 16) out[(size_t)d * NC + c] = t - lse;
}

// ---------------- launch ----------------
extern "C" void kernel_launch(void* const* d_in, const int* in_sizes, int n_in,
                              void* d_out, int out_size){
    const int*   src    = (const int*)  d_in[0];
    const int*   dst    = (const int*)  d_in[1];
    const float* x      = (const float*)d_in[2];
    const float* weights= (const float*)d_in[3];
    const float* latp   = (const float*)d_in[4];
    const float* sl_w   = (const float*)d_in[5];
    const float* sl_b   = (const float*)d_in[6];
    const float* slo_w  = (const float*)d_in[7];
    const float* slo_b  = (const float*)d_in[8];
    const float* fc1_w  = (const float*)d_in[9];
    const float* w_u1   = (const float*)d_in[10];
    const float* w_v1   = (const float*)d_in[11];
    const float* w_s1   = (const float*)d_in[12];
    const float* beta1  = (const float*)d_in[13];
    const float* aw1    = (const float*)d_in[14];
    const float* theta1 = (const float*)d_in[15];
    const float* fc2_w  = (const float*)d_in[16];
    const float* w_u2   = (const float*)d_in[17];
    const float* w_v2   = (const float*)d_in[18];
    const float* w_s2   = (const float*)d_in[19];
    const float* beta2  = (const float*)d_in[20];
    const float* aw2    = (const float*)d_in[21];
    const float* theta2 = (const float*)d_in[22];
    float* out = (float*)d_out;

    // k_gemm1 placed at launch index 3 so ncu's fixed sample slot captures it.
    k_zero<<<1024, 256>>>(beta1, aw1, theta1, beta2, aw2, theta2);
    k_indeg<<<(EE + 255) / 256, 256>>>(dst);
    k_scanA<<<NBLK, 256>>>();
    k_gemm1<<<(NN + 127) / 128, 256>>>(x, fc1_w, w_u1, w_v1);
    k_scanB<<<NBLK, 256>>>();
    k_scatter<<<(EE + 255) / 256, 256>>>(src, dst);
    k_dense2x<<<(NN * NC + 255) / 256, 256>>>(latp, sl_w, sl_b, slo_w, slo_b);
    k_edge1<<<(EE * 8 + 255) / 256, 256>>>(w_s1);
    k_agg1<<<(NN * 32 + 255) / 256, 256>>>();
    k_gemm2n<<<NN / 16, 256>>>(fc2_w, w_u2, w_v2);
    k_edge2<<<(EE + 255) / 256, 256>>>(w_s2, weights);
    k_agg2_final<<<(NN * 32 + 255) / 256, 256>>>(out, out_size);
}

// round 13
// speedup vs baseline: 1.0434x; 1.0434x over previous
#include <cuda_runtime.h>
#include <math.h>

#define NN 50000
#define EE 800000
#define NF 512
#define NH 128
#define NC 16
#define NEG 0.2f
#define FEPS 1e-9f
#define NBLK ((NN + 255) / 256)

// ---------------- scratch layout (floats) ----------------
// zeroed-every-launch region:
#define OUTW1_OFF ((size_t)0)
#define OUTW2_OFF (OUTW1_OFF + NN)
#define CUR_OFF   (OUTW2_OFF + NN)         // int cursors
#define DEG_OFF   (CUR_OFF + NN)           // int in-degree
#define LOSS_OFF  (DEG_OFF + NN)
#define ZERO_TOTAL (LOSS_OFF + 1)
// non-zeroed region:
#define HLATP_OFF  (((ZERO_TOTAL + 3)/4)*4)
#define HLATP2_OFF (HLATP_OFF + (size_t)NN*NC)
#define H1_OFF     (HLATP2_OFF + (size_t)NN*NC)
#define H2_OFF     (H1_OFF + (size_t)NN*NH)
#define RST1_OFF   (H2_OFF + (size_t)NN*NC)
#define EL1_OFF    (RST1_OFF + (size_t)NN*NH)
#define ER1_OFF    (EL1_OFF + NN)
#define EL2_OFF    (ER1_OFF + NN)
#define ER2_OFF    (EL2_OFF + NN)
#define EW_OFF     (ER2_OFF + NN)          // edge weights in CSR order
#define RP_OFF     (EW_OFF + EE)           // int row_ptr[NN+1]
#define CSRC_OFF   (((RP_OFF + NN + 1 + 3)/4)*4)  // int csr_src[EE]
#define CDST_OFF   (CSRC_OFF + EE)         // int csr_dst[EE]
#define EORIG_OFF  (CDST_OFF + EE)         // int csr slot -> orig edge id
#define SC_OFF     (EORIG_OFF + EE)
#define PART_OFF   (SC_OFF + 16)
#define TOTALF     (PART_OFF + NBLK + 16)

__device__ __align__(256) float g_s[TOTALF];

__device__ __forceinline__ float elu1(float x){ return x > 0.f ? x : expf(x) - 1.f; }

// packed f32x2 helpers (sm_100+ PTX; SASS FFMA2 — 2 lane-FMAs per issue)
__device__ __forceinline__ unsigned long long splat2(float a){
    unsigned long long r;
    asm("mov.b64 %0, {%1, %1};" : "=l"(r) : "f"(a));
    return r;
}
__device__ __forceinline__ void fma2(unsigned long long& d, unsigned long long a,
                                     unsigned long long b){
    asm("fma.rn.f32x2 %0, %1, %2, %0;" : "+l"(d) : "l"(a), "l"(b));
}
__device__ __forceinline__ float2 unpack2(unsigned long long v){
    float lo, hi;
    asm("mov.b64 {%0, %1}, %2;" : "=f"(lo), "=f"(hi) : "l"(v));
    return make_float2(lo, hi);
}

// ---------------- zero + scalars ----------------
__global__ void k_zero(const float* b1, const float* a1, const float* t1,
                       const float* b2, const float* a2, const float* t2){
    if (blockIdx.x == 0 && threadIdx.x == 0){
        float* sc = g_s + SC_OFF;
        sc[0] = 2.0f / (expf(-b1[0]) + 1.0f);
        float e0 = expf(a1[0]), e1 = expf(a1[1]);
        sc[1] = e0 / (e0 + e1); sc[2] = e1 / (e0 + e1);
        sc[3] = FEPS / (expf(-t1[0]) + 1.0f);
        sc[4] = 2.0f / (expf(-b2[0]) + 1.0f);
        float f0 = expf(a2[0]), f1 = expf(a2[1]);
        sc[5] = f0 / (f0 + f1); sc[6] = f1 / (f0 + f1);
        sc[7] = FEPS / (expf(-t2[0]) + 1.0f);
    }
    size_t i = (size_t)blockIdx.x * blockDim.x + threadIdx.x;
    size_t stride = (size_t)gridDim.x * blockDim.x;
    for (; i < ZERO_TOTAL; i += stride) g_s[i] = 0.f;
}

__global__ void k_indeg(const int* __restrict__ dst){
    int e = blockIdx.x * blockDim.x + threadIdx.x;
    if (e < EE) atomicAdd((int*)(g_s + DEG_OFF) + dst[e], 1);
}

// ---------------- multi-block scan ----------------
__global__ void k_scanA(){
    __shared__ int wsum[8];
    int lane = threadIdx.x & 31, wid = threadIdx.x >> 5;
    int i = blockIdx.x * 256 + threadIdx.x;
    int v = (i < NN) ? ((const int*)(g_s + DEG_OFF))[i] : 0;
    int x = v;
#pragma unroll
    for (int o = 1; o < 32; o <<= 1){
        int t = __shfl_up_sync(0xffffffffu, x, o);
        if (lane >= o) x += t;
    }
    if (lane == 31) wsum[wid] = x;
    __syncthreads();
    if (threadIdx.x < 8){
        int y = wsum[threadIdx.x];
#pragma unroll
        for (int o = 1; o < 8; o <<= 1){
            int t = __shfl_up_sync(0xffu, y, o);
            if (threadIdx.x >= o) y += t;
        }
        wsum[threadIdx.x] = y;
    }
    __syncthreads();
    int incl = x + (wid ? wsum[wid - 1] : 0);
    if (i < NN) ((int*)(g_s + RP_OFF))[i + 1] = incl;
    if (threadIdx.x == 255) ((int*)(g_s + PART_OFF))[blockIdx.x] = incl;
}

__global__ void k_scanB(){
    __shared__ int off_s;
    if (threadIdx.x == 0) off_s = 0;
    __syncthreads();
    const int* part = (const int*)(g_s + PART_OFF);
    int p = 0;
    for (int j = threadIdx.x; j < blockIdx.x; j += 256) p += part[j];
#pragma unroll
    for (int o = 16; o; o >>= 1) p += __shfl_xor_sync(0xffffffffu, p, o);
    if ((threadIdx.x & 31) == 0 && p) atomicAdd(&off_s, p);
    __syncthreads();
    int i = blockIdx.x * 256 + threadIdx.x;
    if (i < NN) ((int*)(g_s + RP_OFF))[i + 1] += off_s;
    if (blockIdx.x == 0 && threadIdx.x == 0) ((int*)(g_s + RP_OFF))[0] = 0;
}

__global__ void k_scatter(const int* __restrict__ src, const int* __restrict__ dst){
    int e = blockIdx.x * blockDim.x + threadIdx.x;
    if (e >= EE) return;
    int d = dst[e];
    int* cur = (int*)(g_s + CUR_OFF);
    const int* rp = (const int*)(g_s + RP_OFF);
    int p = rp[d] + atomicAdd(&cur[d], 1);
    ((int*)(g_s + CSRC_OFF))[p] = src[e];
    ((int*)(g_s + CDST_OFF))[p] = d;
    ((int*)(g_s + EORIG_OFF))[p] = e;
}

// ---------------- fused double 16x16 dense ----------------
__global__ void k_dense2x(const float* __restrict__ latp,
                          const float* __restrict__ W1, const float* __restrict__ B1,
                          const float* __restrict__ W2, const float* __restrict__ B2){
    __shared__ float W1s[256], W2s[256], bb1[16], bb2[16];
    int t = threadIdx.x;
    W1s[t] = W1[t]; W2s[t] = W2[t];
    if (t < 16){ bb1[t] = B1[t]; bb2[t] = B2[t]; }
    __syncthreads();
    int idx = blockIdx.x * blockDim.x + t;
    if (idx >= NN * NC) return;
    int c = idx & 15;
    float in = latp[idx];
    float acc = bb1[c];
#pragma unroll
    for (int k = 0; k < 16; k++){
        float ik = __shfl_sync(0xffffffffu, in, k, 16);
        acc = fmaf(ik, W1s[k * 16 + c], acc);
    }
    float h = elu1(acc);
    g_s[HLATP_OFF + idx] = h;
    float acc2 = bb2[c];
#pragma unroll
    for (int k = 0; k < 16; k++){
        float hk = __shfl_sync(0xffffffffu, h, k, 16);
        acc2 = fmaf(hk, W2s[k * 16 + c], acc2);
    }
    g_s[HLATP2_OFF + idx] = elu1(acc2);
}

// ---------------- GEMM1 (K-tile 32, f32x2 FMA, LDS.128 b-loads) + fused el1/er1 ----------------
__global__ __launch_bounds__(256) void k_gemm1(const float* __restrict__ A,
                                               const float* __restrict__ B,
                                               const float* __restrict__ wu,
                                               const float* __restrict__ wv){
    __shared__ float As[32][132];
    __shared__ __align__(16) float Bs[32][128];
    int tid = threadIdx.x;
    int m0 = blockIdx.x * 128;
    int tx = tid & 15, ty = tid >> 4;
    unsigned long long accp[8][4];
#pragma unroll
    for (int i = 0; i < 8; i++)
#pragma unroll
        for (int p = 0; p < 4; p++) accp[i][p] = 0ull;

    for (int k0 = 0; k0 < NF; k0 += 32){
#pragma unroll
        for (int l = 0; l < 4; l++){
            int id = tid + l * 256;
            int row = id >> 3, kc = (id & 7) * 4;
            int gm = m0 + row; if (gm >= NN) gm = NN - 1;
            float4 v = *(const float4*)(A + (size_t)gm * NF + k0 + kc);
            As[kc + 0][row] = v.x; As[kc + 1][row] = v.y;
            As[kc + 2][row] = v.z; As[kc + 3][row] = v.w;
        }
#pragma unroll
        for (int l = 0; l < 4; l++){
            int id = tid + l * 256;
            int row = id >> 5, c = (id & 31) * 4;
            float4 v = *(const float4*)(B + (size_t)(k0 + row) * NH + c);
            *(float4*)&Bs[row][c] = v;
        }
        __syncthreads();
#pragma unroll
        for (int kk = 0; kk < 32; kk++){
            float a[8];
            *(float4*)(a)     = *(float4*)&As[kk][ty * 8];
            *(float4*)(a + 4) = *(float4*)&As[kk][ty * 8 + 4];
            // b fragment: 32 contiguous bytes -> two LDS.128
            ulonglong2 q0 = *(const ulonglong2*)&Bs[kk][tx * 8];
            ulonglong2 q1 = *(const ulonglong2*)&Bs[kk][tx * 8 + 4];
#pragma unroll
            for (int i = 0; i < 8; i++){
                unsigned long long ap = splat2(a[i]);
                fma2(accp[i][0], ap, q0.x);
                fma2(accp[i][1], ap, q0.y);
                fma2(accp[i][2], ap, q1.x);
                fma2(accp[i][3], ap, q1.y);
            }
        }
        __syncthreads();
    }
    float wuv[8], wvv[8];
    *(float4*)(wuv)     = ((const float4*)wu)[tx * 2];
    *(float4*)(wuv + 4) = ((const float4*)wu)[tx * 2 + 1];
    *(float4*)(wvv)     = ((const float4*)wv)[tx * 2];
    *(float4*)(wvv + 4) = ((const float4*)wv)[tx * 2 + 1];
#pragma unroll
    for (int i = 0; i < 8; i++){
        int gm = m0 + ty * 8 + i;
        float acc[8];
#pragma unroll
        for (int p = 0; p < 4; p++){
            float2 u = unpack2(accp[i][p]);
            acc[2 * p] = u.x; acc[2 * p + 1] = u.y;
        }
        float ep = 0.f, vp = 0.f;
#pragma unroll
        for (int j = 0; j < 8; j++){
            float cv = acc[j];
            float l = cv > 0.f ? cv : NEG * cv;
            ep = fmaf(l, wuv[j], ep);
            vp = fmaf(l, wvv[j], vp);
        }
#pragma unroll
        for (int o = 1; o < 16; o <<= 1){
            ep += __shfl_xor_sync(0xffffffffu, ep, o);
            vp += __shfl_xor_sync(0xffffffffu, vp, o);
        }
        if (gm < NN){
            float* c = g_s + H1_OFF + (size_t)gm * NH + tx * 8;
            *(float4*)c       = make_float4(acc[0], acc[1], acc[2], acc[3]);
            *(float4*)(c + 4) = make_float4(acc[4], acc[5], acc[6], acc[7]);
            if (tx == 0){ g_s[EL1_OFF + gm] = ep; g_s[ER1_OFF + gm] = vp; }
        }
    }
}

// ---------------- edge pass 1: 8 lanes per edge, CSR slot order ----------------
__global__ void k_edge1(const float* __restrict__ ws){
    int t = blockIdx.x * blockDim.x + threadIdx.x;
    int j = t >> 3, l = t & 7;
    if (j >= EE) return;
    int s = ((const int*)(g_s + CSRC_OFF))[j];
    int d = ((const int*)(g_s + CDST_OFF))[j];
    const float4* hs = (const float4*)(g_s + H1_OFF + (size_t)s * NH);
    const float4* hd = (const float4*)(g_s + H1_OFF + (size_t)d * NH);
    float sdf = 0.f;
#pragma unroll
    for (int q = 0; q < 4; q++){
        float4 a = hs[l + 8 * q];
        float4 b = hd[l + 8 * q];
        float v;
        v = a.x - b.x; sdf = fmaf(v, v, sdf);
        v = a.y - b.y; sdf = fmaf(v, v, sdf);
        v = a.z - b.z; sdf = fmaf(v, v, sdf);
        v = a.w - b.w; sdf = fmaf(v, v, sdf);
    }
    float2 fs = *(const float2*)(g_s + HLATP_OFF + (size_t)s * NC + l * 2);
    float2 fd = *(const float2*)(g_s + HLATP_OFF + (size_t)d * NC + l * 2);
    float2 w2 = *(const float2*)(ws + l * 2);
    float q0 = fs.x - fd.x, q1 = fs.y - fd.y;
    float sds = q0 * q0 + q1 * q1;
    float st = fs.x * w2.x * fd.x + fs.y * w2.y * fd.y;
#pragma unroll
    for (int o = 4; o; o >>= 1){
        sdf += __shfl_xor_sync(0xffffffffu, sdf, o);
        sds += __shfl_xor_sync(0xffffffffu, sds, o);
        st  += __shfl_xor_sync(0xffffffffu, st,  o);
    }
    if (l == 0){
        const float* sc = g_s + SC_OFF;
        float ev = g_s[EL1_OFF + s] + g_s[ER1_OFF + d] + st;
        float dd = sc[1] * sdf + sc[2] * sds;
        float ew = expf(ev - sc[0] * dd) + FEPS;
        g_s[EW_OFF + j] = ew;
        atomicAdd(&g_s[OUTW1_OFF + s], ew);
    }
}

// ---------------- CSR aggregation layer1 (inw computed in-warp) ----------------
__global__ void k_agg1(){
    int d = (blockIdx.x * blockDim.x + threadIdx.x) >> 5;
    int lane = threadIdx.x & 31;
    if (d >= NN) return;
    const int* rp = (const int*)(g_s + RP_OFF);
    const int* cs = (const int*)(g_s + CSRC_OFF);
    const float* ewc = g_s + EW_OFF;
    int b = rp[d], eend = rp[d + 1];
    float s_ew = 0.f;
    for (int j = b + lane; j < eend; j += 32) s_ew += ewc[j];
#pragma unroll
    for (int o = 16; o; o >>= 1) s_ew += __shfl_xor_sync(0xffffffffu, s_ew, o);
    float inw_r = rsqrtf(s_ew);
    float4 A = make_float4(0.f, 0.f, 0.f, 0.f);
    float4 Bc = make_float4(0.f, 0.f, 0.f, 0.f);
    int j = b;
    for (; j + 3 < eend; j += 4){
        int s0 = cs[j], s1 = cs[j + 1], s2 = cs[j + 2], s3 = cs[j + 3];
        float a0 = inw_r * rsqrtf(g_s[OUTW1_OFF + s0]) * ewc[j];
        float a1 = inw_r * rsqrtf(g_s[OUTW1_OFF + s1]) * ewc[j + 1];
        float a2 = inw_r * rsqrtf(g_s[OUTW1_OFF + s2]) * ewc[j + 2];
        float a3 = inw_r * rsqrtf(g_s[OUTW1_OFF + s3]) * ewc[j + 3];
        float4 h0 = ((const float4*)(g_s + H1_OFF + (size_t)s0 * NH))[lane];
        float4 h1 = ((const float4*)(g_s + H1_OFF + (size_t)s1 * NH))[lane];
        float4 h2 = ((const float4*)(g_s + H1_OFF + (size_t)s2 * NH))[lane];
        float4 h3 = ((const float4*)(g_s + H1_OFF + (size_t)s3 * NH))[lane];
        A.x = fmaf(h0.x, a0, A.x); A.y = fmaf(h0.y, a0, A.y);
        A.z = fmaf(h0.z, a0, A.z); A.w = fmaf(h0.w, a0, A.w);
        Bc.x = fmaf(h1.x, a1, Bc.x); Bc.y = fmaf(h1.y, a1, Bc.y);
        Bc.z = fmaf(h1.z, a1, Bc.z); Bc.w = fmaf(h1.w, a1, Bc.w);
        A.x = fmaf(h2.x, a2, A.x); A.y = fmaf(h2.y, a2, A.y);
        A.z = fmaf(h2.z, a2, A.z); A.w = fmaf(h2.w, a2, A.w);
        Bc.x = fmaf(h3.x, a3, Bc.x); Bc.y = fmaf(h3.y, a3, Bc.y);
        Bc.z = fmaf(h3.z, a3, Bc.z); Bc.w = fmaf(h3.w, a3, Bc.w);
    }
    for (; j < eend; j++){
        int s0 = cs[j];
        float a0 = inw_r * rsqrtf(g_s[OUTW1_OFF + s0]) * ewc[j];
        float4 h0 = ((const float4*)(g_s + H1_OFF + (size_t)s0 * NH))[lane];
        A.x = fmaf(h0.x, a0, A.x); A.y = fmaf(h0.y, a0, A.y);
        A.z = fmaf(h0.z, a0, A.z); A.w = fmaf(h0.w, a0, A.w);
    }
    float perm = g_s[SC_OFF + 3] / ((float)(eend - b) + FEPS);
    float4 hd = ((const float4*)(g_s + H1_OFF + (size_t)d * NH))[lane];
    float4 r;
    r.x = elu1(A.x + Bc.x + hd.x * perm);
    r.y = elu1(A.y + Bc.y + hd.y * perm);
    r.z = elu1(A.z + Bc.z + hd.z * perm);
    r.w = elu1(A.w + Bc.w + hd.w * perm);
    ((float4*)(g_s + RST1_OFF + (size_t)d * NH))[lane] = r;
}

// ---------------- GEMM2 (smem-tiled) + fused el2/er2 ----------------
__global__ __launch_bounds__(256) void k_gemm2n(const float* __restrict__ W,
                                                const float* __restrict__ wu,
                                                const float* __restrict__ wv){
    __shared__ float Ws[NH * NC];
    __shared__ float Rs[16][NH];
    int tid = threadIdx.x;
    for (int i = tid; i < NH * NC; i += 256) Ws[i] = W[i];
    int nb = blockIdx.x * 16;
#pragma unroll
    for (int it = 0; it < 8; it++){
        int i = tid + it * 256;
        int row = i >> 7, col = i & 127;
        Rs[row][col] = g_s[RST1_OFF + (size_t)(nb + row) * NH + col];
    }
    __syncthreads();
    int nl = tid >> 4, c = tid & 15;
    float acc = 0.f;
#pragma unroll
    for (int k = 0; k < NH; k++) acc = fmaf(Rs[nl][k], Ws[k * 16 + c], acc);
    int n = nb + nl;
    g_s[H2_OFF + (size_t)n * NC + c] = acc;
    float l = acc > 0.f ? acc : NEG * acc;
    float up = l * wu[c], vp = l * wv[c];
#pragma unroll
    for (int o = 8; o; o >>= 1){
        up += __shfl_xor_sync(0xffffffffu, up, o);
        vp += __shfl_xor_sync(0xffffffffu, vp, o);
    }
    if (c == 0){ g_s[EL2_OFF + n] = up; g_s[ER2_OFF + n] = vp; }
}

// ---------------- edge pass 2 (+ loss fused), CSR slot order ----------------
__global__ void k_edge2(const float* __restrict__ ws, const float* __restrict__ lw){
    int j = blockIdx.x * blockDim.x + threadIdx.x;
    float lacc = 0.f;
    if (j < EE){
        int s = ((const int*)(g_s + CSRC_OFF))[j];
        int d = ((const int*)(g_s + CDST_OFF))[j];
        const float4* hs = (const float4*)(g_s + H2_OFF + (size_t)s * NC);
        const float4* hd = (const float4*)(g_s + H2_OFF + (size_t)d * NC);
        const float4* fs = (const float4*)(g_s + HLATP2_OFF + (size_t)s * NC);
        const float4* fd = (const float4*)(g_s + HLATP2_OFF + (size_t)d * NC);
        const float4* w4 = (const float4*)ws;
        float sdf = 0.f, sds = 0.f, st = 0.f, pdot = 0.f;
#pragma unroll
        for (int q = 0; q < 4; q++){
            float4 a = hs[q], b = hd[q];
            float v;
            v = a.x - b.x; sdf += v * v;
            v = a.y - b.y; sdf += v * v;
            v = a.z - b.z; sdf += v * v;
            v = a.w - b.w; sdf += v * v;
            float4 p = fs[q], r = fd[q], w = w4[q];
            v = p.x - r.x; sds += v * v;
            v = p.y - r.y; sds += v * v;
            v = p.z - r.z; sds += v * v;
            v = p.w - r.w; sds += v * v;
            st += p.x * w.x * r.x + p.y * w.y * r.y + p.z * w.z * r.z + p.w * w.w * r.w;
            pdot += p.x * r.x + p.y * r.y + p.z * r.z + p.w * r.w;
        }
        const float* sc = g_s + SC_OFF;
        float ev = g_s[EL2_OFF + s] + g_s[ER2_OFF + d] + st;
        float ew = expf(ev - sc[4] * (sc[5] * sdf + sc[6] * sds)) + FEPS;
        g_s[EW_OFF + j] = ew;
        atomicAdd(&g_s[OUTW2_OFF + s], ew);
        lacc = lw[((const int*)(g_s + EORIG_OFF))[j]] * pdot;
    }
#pragma unroll
    for (int o = 16; o; o >>= 1) lacc += __shfl_xor_sync(0xffffffffu, lacc, o);
    if ((threadIdx.x & 31) == 0) atomicAdd(&g_s[LOSS_OFF], lacc);
}

// ---------------- CSR aggregation layer2 + final log-softmax ----------------
__global__ void k_agg2_final(float* __restrict__ out, int out_size){
    int d = (blockIdx.x * blockDim.x + threadIdx.x) >> 5;
    int lane = threadIdx.x & 31;
    if (d >= NN) return;
    if (d == 0 && lane == 0 && out_size > NN * NC) out[NN * NC] = g_s[LOSS_OFF];
    const int* rp = (const int*)(g_s + RP_OFF);
    const int* cs = (const int*)(g_s + CSRC_OFF);
    const float* ewc = g_s + EW_OFF;
    int b = rp[d], eend = rp[d + 1];
    int c = lane & 15;
    int half = lane >> 4;
    float s_ew = 0.f;
    for (int j = b + lane; j < eend; j += 32) s_ew += ewc[j];
#pragma unroll
    for (int o = 16; o; o >>= 1) s_ew += __shfl_xor_sync(0xffffffffu, s_ew, o);
    float inw_r = rsqrtf(s_ew);
    float acc = 0.f;
    for (int j = b + half; j < eend; j += 2){
        int s = cs[j];
        float a = inw_r * rsqrtf(g_s[OUTW2_OFF + s]) * ewc[j];
        acc = fmaf(g_s[H2_OFF + (size_t)s * NC + c], a, acc);
    }
    acc += __shfl_xor_sync(0xffffffffu, acc, 16);
    float perm = g_s[SC_OFF + 7] / ((float)(eend - b) + FEPS);
    float t = elu1(acc + g_s[H2_OFF + (size_t)d * NC + c] * perm);
    float mx = t;
#pragma unroll
    for (int o = 8; o; o >>= 1) mx = fmaxf(mx, __shfl_xor_sync(0xffffffffu, mx, o));
    float s2 = expf(t - mx);
#pragma unroll
    for (int o = 8; o; o >>= 1) s2 += __shfl_xor_sync(0xffffffffu, s2, o);
    float lse = mx + logf(s2);
    if (lane < 16) out[(size_t)d * NC + c] = t - lse;
}

// ---------------- launch ----------------
extern "C" void kernel_launch(void* const* d_in, const int* in_sizes, int n_in,
                              void* d_out, int out_size){
    const int*   src    = (const int*)  d_in[0];
    const int*   dst    = (const int*)  d_in[1];
    const float* x      = (const float*)d_in[2];
    const float* weights= (const float*)d_in[3];
    const float* latp   = (const float*)d_in[4];
    const float* sl_w   = (const float*)d_in[5];
    const float* sl_b   = (const float*)d_in[6];
    const float* slo_w  = (const float*)d_in[7];
    const float* slo_b  = (const float*)d_in[8];
    const float* fc1_w  = (const float*)d_in[9];
    const float* w_u1   = (const float*)d_in[10];
    const float* w_v1   = (const float*)d_in[11];
    const float* w_s1   = (const float*)d_in[12];
    const float* beta1  = (const float*)d_in[13];
    const float* aw1    = (const float*)d_in[14];
    const float* theta1 = (const float*)d_in[15];
    const float* fc2_w  = (const float*)d_in[16];
    const float* w_u2   = (const float*)d_in[17];
    const float* w_v2   = (const float*)d_in[18];
    const float* w_s2   = (const float*)d_in[19];
    const float* beta2  = (const float*)d_in[20];
    const float* aw2    = (const float*)d_in[21];
    const float* theta2 = (const float*)d_in[22];
    float* out = (float*)d_out;

    // k_gemm1 at launch index 3 so ncu's fixed sample slot captures it.
    k_zero<<<1024, 256>>>(beta1, aw1, theta1, beta2, aw2, theta2);
    k_indeg<<<(EE + 255) / 256, 256>>>(dst);
    k_scanA<<<NBLK, 256>>>();
    k_gemm1<<<(NN + 127) / 128, 256>>>(x, fc1_w, w_u1, w_v1);
    k_scanB<<<NBLK, 256>>>();
    k_scatter<<<(EE + 255) / 256, 256>>>(src, dst);
    k_dense2x<<<(NN * NC + 255) / 256, 256>>>(latp, sl_w, sl_b, slo_w, slo_b);
    k_edge1<<<(EE * 8 + 255) / 256, 256>>>(w_s1);
    k_agg1<<<(NN * 32 + 255) / 256, 256>>>();
    k_gemm2n<<<NN / 16, 256>>>(fc2_w, w_u2, w_v2);
    k_edge2<<<(EE + 255) / 256, 256>>>(w_s2, weights);
    k_agg2_final<<<(NN * 32 + 255) / 256, 256>>>(out, out_size);
}

// round 14
// speedup vs baseline: 1.0584x; 1.0144x over previous
#include <cuda_runtime.h>
#include <math.h>

#define NN 50000
#define EE 800000
#define NF 512
#define NH 128
#define NC 16
#define NEG 0.2f
#define FEPS 1e-9f
#define NBLK ((NN + 255) / 256)

// ---------------- scratch layout (floats) ----------------
// zeroed-every-launch region:
#define OUTW1_OFF ((size_t)0)
#define OUTW2_OFF (OUTW1_OFF + NN)
#define CUR_OFF   (OUTW2_OFF + NN)         // int cursors
#define DEG_OFF   (CUR_OFF + NN)           // int in-degree
#define LOSS_OFF  (DEG_OFF + NN)
#define ZERO_TOTAL (LOSS_OFF + 1)
// non-zeroed region:
#define HLATP_OFF  (((ZERO_TOTAL + 3)/4)*4)
#define HLATP2_OFF (HLATP_OFF + (size_t)NN*NC)
#define H1_OFF     (HLATP2_OFF + (size_t)NN*NC)
#define H2_OFF     (H1_OFF + (size_t)NN*NH)
#define RST1_OFF   (H2_OFF + (size_t)NN*NC)
#define EL1_OFF    (RST1_OFF + (size_t)NN*NH)
#define ER1_OFF    (EL1_OFF + NN)
#define EL2_OFF    (ER1_OFF + NN)
#define ER2_OFF    (EL2_OFF + NN)
#define EW_OFF     (ER2_OFF + NN)          // edge weights in CSR order
#define RP_OFF     (EW_OFF + EE)           // int row_ptr[NN+1]
#define CSRC_OFF   (((RP_OFF + NN + 1 + 3)/4)*4)  // int csr_src[EE]
#define CDST_OFF   (CSRC_OFF + EE)         // int csr_dst[EE]
#define EORIG_OFF  (CDST_OFF + EE)         // int csr slot -> orig edge id
#define SC_OFF     (EORIG_OFF + EE)
#define PART_OFF   (SC_OFF + 16)
#define TOTALF     (PART_OFF + NBLK + 16)

__device__ __align__(256) float g_s[TOTALF];

__device__ __forceinline__ float elu1(float x){ return x > 0.f ? x : expf(x) - 1.f; }

// packed f32x2 helpers (sm_100+ PTX; SASS FFMA2 — 2 lane-FMAs per issue)
__device__ __forceinline__ unsigned long long splat2(float a){
    unsigned long long r;
    asm("mov.b64 %0, {%1, %1};" : "=l"(r) : "f"(a));
    return r;
}
__device__ __forceinline__ void fma2(unsigned long long& d, unsigned long long a,
                                     unsigned long long b){
    asm("fma.rn.f32x2 %0, %1, %2, %0;" : "+l"(d) : "l"(a), "l"(b));
}
__device__ __forceinline__ float2 unpack2(unsigned long long v){
    float lo, hi;
    asm("mov.b64 {%0, %1}, %2;" : "=f"(lo), "=f"(hi) : "l"(v));
    return make_float2(lo, hi);
}

// ---------------- zero + scalars ----------------
__global__ void k_zero(const float* b1, const float* a1, const float* t1,
                       const float* b2, const float* a2, const float* t2){
    if (blockIdx.x == 0 && threadIdx.x == 0){
        float* sc = g_s + SC_OFF;
        sc[0] = 2.0f / (expf(-b1[0]) + 1.0f);
        float e0 = expf(a1[0]), e1 = expf(a1[1]);
        sc[1] = e0 / (e0 + e1); sc[2] = e1 / (e0 + e1);
        sc[3] = FEPS / (expf(-t1[0]) + 1.0f);
        sc[4] = 2.0f / (expf(-b2[0]) + 1.0f);
        float f0 = expf(a2[0]), f1 = expf(a2[1]);
        sc[5] = f0 / (f0 + f1); sc[6] = f1 / (f0 + f1);
        sc[7] = FEPS / (expf(-t2[0]) + 1.0f);
    }
    size_t i = (size_t)blockIdx.x * blockDim.x + threadIdx.x;
    size_t stride = (size_t)gridDim.x * blockDim.x;
    for (; i < ZERO_TOTAL; i += stride) g_s[i] = 0.f;
}

__global__ void k_indeg(const int* __restrict__ dst){
    int e = blockIdx.x * blockDim.x + threadIdx.x;
    if (e < EE) atomicAdd((int*)(g_s + DEG_OFF) + dst[e], 1);
}

// ---------------- multi-block scan ----------------
__global__ void k_scanA(){
    __shared__ int wsum[8];
    int lane = threadIdx.x & 31, wid = threadIdx.x >> 5;
    int i = blockIdx.x * 256 + threadIdx.x;
    int v = (i < NN) ? ((const int*)(g_s + DEG_OFF))[i] : 0;
    int x = v;
#pragma unroll
    for (int o = 1; o < 32; o <<= 1){
        int t = __shfl_up_sync(0xffffffffu, x, o);
        if (lane >= o) x += t;
    }
    if (lane == 31) wsum[wid] = x;
    __syncthreads();
    if (threadIdx.x < 8){
        int y = wsum[threadIdx.x];
#pragma unroll
        for (int o = 1; o < 8; o <<= 1){
            int t = __shfl_up_sync(0xffu, y, o);
            if (threadIdx.x >= o) y += t;
        }
        wsum[threadIdx.x] = y;
    }
    __syncthreads();
    int incl = x + (wid ? wsum[wid - 1] : 0);
    if (i < NN) ((int*)(g_s + RP_OFF))[i + 1] = incl;
    if (threadIdx.x == 255) ((int*)(g_s + PART_OFF))[blockIdx.x] = incl;
}

__global__ void k_scanB(){
    __shared__ int off_s;
    if (threadIdx.x == 0) off_s = 0;
    __syncthreads();
    const int* part = (const int*)(g_s + PART_OFF);
    int p = 0;
    for (int j = threadIdx.x; j < blockIdx.x; j += 256) p += part[j];
#pragma unroll
    for (int o = 16; o; o >>= 1) p += __shfl_xor_sync(0xffffffffu, p, o);
    if ((threadIdx.x & 31) == 0 && p) atomicAdd(&off_s, p);
    __syncthreads();
    int i = blockIdx.x * 256 + threadIdx.x;
    if (i < NN) ((int*)(g_s + RP_OFF))[i + 1] += off_s;
    if (blockIdx.x == 0 && threadIdx.x == 0) ((int*)(g_s + RP_OFF))[0] = 0;
}

__global__ void k_scatter(const int* __restrict__ src, const int* __restrict__ dst){
    int e = blockIdx.x * blockDim.x + threadIdx.x;
    if (e >= EE) return;
    int d = dst[e];
    int* cur = (int*)(g_s + CUR_OFF);
    const int* rp = (const int*)(g_s + RP_OFF);
    int p = rp[d] + atomicAdd(&cur[d], 1);
    ((int*)(g_s + CSRC_OFF))[p] = src[e];
    ((int*)(g_s + CDST_OFF))[p] = d;
    ((int*)(g_s + EORIG_OFF))[p] = e;
}

// ---------------- fused double 16x16 dense ----------------
__global__ void k_dense2x(const float* __restrict__ latp,
                          const float* __restrict__ W1, const float* __restrict__ B1,
                          const float* __restrict__ W2, const float* __restrict__ B2){
    __shared__ float W1s[256], W2s[256], bb1[16], bb2[16];
    int t = threadIdx.x;
    W1s[t] = W1[t]; W2s[t] = W2[t];
    if (t < 16){ bb1[t] = B1[t]; bb2[t] = B2[t]; }
    __syncthreads();
    int idx = blockIdx.x * blockDim.x + t;
    if (idx >= NN * NC) return;
    int c = idx & 15;
    float in = latp[idx];
    float acc = bb1[c];
#pragma unroll
    for (int k = 0; k < 16; k++){
        float ik = __shfl_sync(0xffffffffu, in, k, 16);
        acc = fmaf(ik, W1s[k * 16 + c], acc);
    }
    float h = elu1(acc);
    g_s[HLATP_OFF + idx] = h;
    float acc2 = bb2[c];
#pragma unroll
    for (int k = 0; k < 16; k++){
        float hk = __shfl_sync(0xffffffffu, h, k, 16);
        acc2 = fmaf(hk, W2s[k * 16 + c], acc2);
    }
    g_s[HLATP2_OFF + idx] = elu1(acc2);
}

// ---------------- GEMM1 (K-tile 32, f32x2, 16m x 4n thread tile) + fused el1/er1 ----------------
// warp covers all 128 n exactly once (tx = lane, 4 n each) -> b-fragment LDS
// perfectly packed; a-fragments warp-broadcast (ty uniform per warp).
__global__ __launch_bounds__(256) void k_gemm1(const float* __restrict__ A,
                                               const float* __restrict__ B,
                                               const float* __restrict__ wu,
                                               const float* __restrict__ wv){
    __shared__ float As[32][132];
    __shared__ __align__(16) float Bs[32][128];
    int tid = threadIdx.x;
    int m0 = blockIdx.x * 128;
    int tx = tid & 31, ty = tid >> 5;          // 32 n-threads x 8 m-warps
    unsigned long long accp[16][2];
#pragma unroll
    for (int i = 0; i < 16; i++){ accp[i][0] = 0ull; accp[i][1] = 0ull; }

    for (int k0 = 0; k0 < NF; k0 += 32){
#pragma unroll
        for (int l = 0; l < 4; l++){
            int id = tid + l * 256;
            int row = id >> 3, kc = (id & 7) * 4;
            int gm = m0 + row; if (gm >= NN) gm = NN - 1;
            float4 v = *(const float4*)(A + (size_t)gm * NF + k0 + kc);
            As[kc + 0][row] = v.x; As[kc + 1][row] = v.y;
            As[kc + 2][row] = v.z; As[kc + 3][row] = v.w;
        }
#pragma unroll
        for (int l = 0; l < 4; l++){
            int id = tid + l * 256;
            int row = id >> 5, c = (id & 31) * 4;
            float4 v = *(const float4*)(B + (size_t)(k0 + row) * NH + c);
            *(float4*)&Bs[row][c] = v;
        }
        __syncthreads();
#pragma unroll
        for (int kk = 0; kk < 32; kk++){
            float a[16];
            *(float4*)(a)      = *(float4*)&As[kk][ty * 16];
            *(float4*)(a + 4)  = *(float4*)&As[kk][ty * 16 + 4];
            *(float4*)(a + 8)  = *(float4*)&As[kk][ty * 16 + 8];
            *(float4*)(a + 12) = *(float4*)&As[kk][ty * 16 + 12];
            ulonglong2 q = *(const ulonglong2*)&Bs[kk][tx * 4];
#pragma unroll
            for (int i = 0; i < 16; i++){
                unsigned long long ap = splat2(a[i]);
                fma2(accp[i][0], ap, q.x);
                fma2(accp[i][1], ap, q.y);
            }
        }
        __syncthreads();
    }
    float4 wu4 = ((const float4*)wu)[tx];
    float4 wv4 = ((const float4*)wv)[tx];
#pragma unroll
    for (int i = 0; i < 16; i++){
        int gm = m0 + ty * 16 + i;
        float2 u0 = unpack2(accp[i][0]);
        float2 u1 = unpack2(accp[i][1]);
        float l0 = u0.x > 0.f ? u0.x : NEG * u0.x;
        float l1 = u0.y > 0.f ? u0.y : NEG * u0.y;
        float l2 = u1.x > 0.f ? u1.x : NEG * u1.x;
        float l3 = u1.y > 0.f ? u1.y : NEG * u1.y;
        float ep = l0 * wu4.x + l1 * wu4.y + l2 * wu4.z + l3 * wu4.w;
        float vp = l0 * wv4.x + l1 * wv4.y + l2 * wv4.z + l3 * wv4.w;
#pragma unroll
        for (int o = 1; o < 32; o <<= 1){
            ep += __shfl_xor_sync(0xffffffffu, ep, o);
            vp += __shfl_xor_sync(0xffffffffu, vp, o);
        }
        if (gm < NN){
            *(float4*)(g_s + H1_OFF + (size_t)gm * NH + tx * 4) =
                make_float4(u0.x, u0.y, u1.x, u1.y);
            if (tx == 0){ g_s[EL1_OFF + gm] = ep; g_s[ER1_OFF + gm] = vp; }
        }
    }
}

// ---------------- edge pass 1: 8 lanes per edge, CSR slot order ----------------
__global__ void k_edge1(const float* __restrict__ ws){
    int t = blockIdx.x * blockDim.x + threadIdx.x;
    int j = t >> 3, l = t & 7;
    if (j >= EE) return;
    int s = ((const int*)(g_s + CSRC_OFF))[j];
    int d = ((const int*)(g_s + CDST_OFF))[j];
    const float4* hs = (const float4*)(g_s + H1_OFF + (size_t)s * NH);
    const float4* hd = (const float4*)(g_s + H1_OFF + (size_t)d * NH);
    float sdf = 0.f;
#pragma unroll
    for (int q = 0; q < 4; q++){
        float4 a = hs[l + 8 * q];
        float4 b = hd[l + 8 * q];
        float v;
        v = a.x - b.x; sdf = fmaf(v, v, sdf);
        v = a.y - b.y; sdf = fmaf(v, v, sdf);
        v = a.z - b.z; sdf = fmaf(v, v, sdf);
        v = a.w - b.w; sdf = fmaf(v, v, sdf);
    }
    float2 fs = *(const float2*)(g_s + HLATP_OFF + (size_t)s * NC + l * 2);
    float2 fd = *(const float2*)(g_s + HLATP_OFF + (size_t)d * NC + l * 2);
    float2 w2 = *(const float2*)(ws + l * 2);
    float q0 = fs.x - fd.x, q1 = fs.y - fd.y;
    float sds = q0 * q0 + q1 * q1;
    float st = fs.x * w2.x * fd.x + fs.y * w2.y * fd.y;
#pragma unroll
    for (int o = 4; o; o >>= 1){
        sdf += __shfl_xor_sync(0xffffffffu, sdf, o);
        sds += __shfl_xor_sync(0xffffffffu, sds, o);
        st  += __shfl_xor_sync(0xffffffffu, st,  o);
    }
    if (l == 0){
        const float* sc = g_s + SC_OFF;
        float ev = g_s[EL1_OFF + s] + g_s[ER1_OFF + d] + st;
        float dd = sc[1] * sdf + sc[2] * sds;
        float ew = expf(ev - sc[0] * dd) + FEPS;
        g_s[EW_OFF + j] = ew;
        atomicAdd(&g_s[OUTW1_OFF + s], ew);
    }
}

// ---------------- CSR aggregation layer1 (inw computed in-warp) ----------------
__global__ void k_agg1(){
    int d = (blockIdx.x * blockDim.x + threadIdx.x) >> 5;
    int lane = threadIdx.x & 31;
    if (d >= NN) return;
    const int* rp = (const int*)(g_s + RP_OFF);
    const int* cs = (const int*)(g_s + CSRC_OFF);
    const float* ewc = g_s + EW_OFF;
    int b = rp[d], eend = rp[d + 1];
    float s_ew = 0.f;
    for (int j = b + lane; j < eend; j += 32) s_ew += ewc[j];
#pragma unroll
    for (int o = 16; o; o >>= 1) s_ew += __shfl_xor_sync(0xffffffffu, s_ew, o);
    float inw_r = rsqrtf(s_ew);
    float4 A = make_float4(0.f, 0.f, 0.f, 0.f);
    float4 Bc = make_float4(0.f, 0.f, 0.f, 0.f);
    int j = b;
    for (; j + 3 < eend; j += 4){
        int s0 = cs[j], s1 = cs[j + 1], s2 = cs[j + 2], s3 = cs[j + 3];
        float a0 = inw_r * rsqrtf(g_s[OUTW1_OFF + s0]) * ewc[j];
        float a1 = inw_r * rsqrtf(g_s[OUTW1_OFF + s1]) * ewc[j + 1];
        float a2 = inw_r * rsqrtf(g_s[OUTW1_OFF + s2]) * ewc[j + 2];
        float a3 = inw_r * rsqrtf(g_s[OUTW1_OFF + s3]) * ewc[j + 3];
        float4 h0 = ((const float4*)(g_s + H1_OFF + (size_t)s0 * NH))[lane];
        float4 h1 = ((const float4*)(g_s + H1_OFF + (size_t)s1 * NH))[lane];
        float4 h2 = ((const float4*)(g_s + H1_OFF + (size_t)s2 * NH))[lane];
        float4 h3 = ((const float4*)(g_s + H1_OFF + (size_t)s3 * NH))[lane];
        A.x = fmaf(h0.x, a0, A.x); A.y = fmaf(h0.y, a0, A.y);
        A.z = fmaf(h0.z, a0, A.z); A.w = fmaf(h0.w, a0, A.w);
        Bc.x = fmaf(h1.x, a1, Bc.x); Bc.y = fmaf(h1.y, a1, Bc.y);
        Bc.z = fmaf(h1.z, a1, Bc.z); Bc.w = fmaf(h1.w, a1, Bc.w);
        A.x = fmaf(h2.x, a2, A.x); A.y = fmaf(h2.y, a2, A.y);
        A.z = fmaf(h2.z, a2, A.z); A.w = fmaf(h2.w, a2, A.w);
        Bc.x = fmaf(h3.x, a3, Bc.x); Bc.y = fmaf(h3.y, a3, Bc.y);
        Bc.z = fmaf(h3.z, a3, Bc.z); Bc.w = fmaf(h3.w, a3, Bc.w);
    }
    for (; j < eend; j++){
        int s0 = cs[j];
        float a0 = inw_r * rsqrtf(g_s[OUTW1_OFF + s0]) * ewc[j];
        float4 h0 = ((const float4*)(g_s + H1_OFF + (size_t)s0 * NH))[lane];
        A.x = fmaf(h0.x, a0, A.x); A.y = fmaf(h0.y, a0, A.y);
        A.z = fmaf(h0.z, a0, A.z); A.w = fmaf(h0.w, a0, A.w);
    }
    float perm = g_s[SC_OFF + 3] / ((float)(eend - b) + FEPS);
    float4 hd = ((const float4*)(g_s + H1_OFF + (size_t)d * NH))[lane];
    float4 r;
    r.x = elu1(A.x + Bc.x + hd.x * perm);
    r.y = elu1(A.y + Bc.y + hd.y * perm);
    r.z = elu1(A.z + Bc.z + hd.z * perm);
    r.w = elu1(A.w + Bc.w + hd.w * perm);
    ((float4*)(g_s + RST1_OFF + (size_t)d * NH))[lane] = r;
}

// ---------------- GEMM2 (smem-tiled) + fused el2/er2 ----------------
__global__ __launch_bounds__(256) void k_gemm2n(const float* __restrict__ W,
                                                const float* __restrict__ wu,
                                                const float* __restrict__ wv){
    __shared__ float Ws[NH * NC];
    __shared__ float Rs[16][NH];
    int tid = threadIdx.x;
    for (int i = tid; i < NH * NC; i += 256) Ws[i] = W[i];
    int nb = blockIdx.x * 16;
#pragma unroll
    for (int it = 0; it < 8; it++){
        int i = tid + it * 256;
        int row = i >> 7, col = i & 127;
        Rs[row][col] = g_s[RST1_OFF + (size_t)(nb + row) * NH + col];
    }
    __syncthreads();
    int nl = tid >> 4, c = tid & 15;
    float acc = 0.f;
#pragma unroll
    for (int k = 0; k < NH; k++) acc = fmaf(Rs[nl][k], Ws[k * 16 + c], acc);
    int n = nb + nl;
    g_s[H2_OFF + (size_t)n * NC + c] = acc;
    float l = acc > 0.f ? acc : NEG * acc;
    float up = l * wu[c], vp = l * wv[c];
#pragma unroll
    for (int o = 8; o; o >>= 1){
        up += __shfl_xor_sync(0xffffffffu, up, o);
        vp += __shfl_xor_sync(0xffffffffu, vp, o);
    }
    if (c == 0){ g_s[EL2_OFF + n] = up; g_s[ER2_OFF + n] = vp; }
}

// ---------------- edge pass 2 (+ loss fused), CSR slot order ----------------
__global__ void k_edge2(const float* __restrict__ ws, const float* __restrict__ lw){
    int j = blockIdx.x * blockDim.x + threadIdx.x;
    float lacc = 0.f;
    if (j < EE){
        int s = ((const int*)(g_s + CSRC_OFF))[j];
        int d = ((const int*)(g_s + CDST_OFF))[j];
        const float4* hs = (const float4*)(g_s + H2_OFF + (size_t)s * NC);
        const float4* hd = (const float4*)(g_s + H2_OFF + (size_t)d * NC);
        const float4* fs = (const float4*)(g_s + HLATP2_OFF + (size_t)s * NC);
        const float4* fd = (const float4*)(g_s + HLATP2_OFF + (size_t)d * NC);
        const float4* w4 = (const float4*)ws;
        float sdf = 0.f, sds = 0.f, st = 0.f, pdot = 0.f;
#pragma unroll
        for (int q = 0; q < 4; q++){
            float4 a = hs[q], b = hd[q];
            float v;
            v = a.x - b.x; sdf += v * v;
            v = a.y - b.y; sdf += v * v;
            v = a.z - b.z; sdf += v * v;
            v = a.w - b.w; sdf += v * v;
            float4 p = fs[q], r = fd[q], w = w4[q];
            v = p.x - r.x; sds += v * v;
            v = p.y - r.y; sds += v * v;
            v = p.z - r.z; sds += v * v;
            v = p.w - r.w; sds += v * v;
            st += p.x * w.x * r.x + p.y * w.y * r.y + p.z * w.z * r.z + p.w * w.w * r.w;
            pdot += p.x * r.x + p.y * r.y + p.z * r.z + p.w * r.w;
        }
        const float* sc = g_s + SC_OFF;
        float ev = g_s[EL2_OFF + s] + g_s[ER2_OFF + d] + st;
        float ew = expf(ev - sc[4] * (sc[5] * sdf + sc[6] * sds)) + FEPS;
        g_s[EW_OFF + j] = ew;
        atomicAdd(&g_s[OUTW2_OFF + s], ew);
        lacc = lw[((const int*)(g_s + EORIG_OFF))[j]] * pdot;
    }
#pragma unroll
    for (int o = 16; o; o >>= 1) lacc += __shfl_xor_sync(0xffffffffu, lacc, o);
    if ((threadIdx.x & 31) == 0) atomicAdd(&g_s[LOSS_OFF], lacc);
}

// ---------------- CSR aggregation layer2 + final log-softmax ----------------
__global__ void k_agg2_final(float* __restrict__ out, int out_size){
    int d = (blockIdx.x * blockDim.x + threadIdx.x) >> 5;
    int lane = threadIdx.x & 31;
    if (d >= NN) return;
    if (d == 0 && lane == 0 && out_size > NN * NC) out[NN * NC] = g_s[LOSS_OFF];
    const int* rp = (const int*)(g_s + RP_OFF);
    const int* cs = (const int*)(g_s + CSRC_OFF);
    const float* ewc = g_s + EW_OFF;
    int b = rp[d], eend = rp[d + 1];
    int c = lane & 15;
    int half = lane >> 4;
    float s_ew = 0.f;
    for (int j = b + lane; j < eend; j += 32) s_ew += ewc[j];
#pragma unroll
    for (int o = 16; o; o >>= 1) s_ew += __shfl_xor_sync(0xffffffffu, s_ew, o);
    float inw_r = rsqrtf(s_ew);
    float acc = 0.f;
    for (int j = b + half; j < eend; j += 2){
        int s = cs[j];
        float a = inw_r * rsqrtf(g_s[OUTW2_OFF + s]) * ewc[j];
        acc = fmaf(g_s[H2_OFF + (size_t)s * NC + c], a, acc);
    }
    acc += __shfl_xor_sync(0xffffffffu, acc, 16);
    float perm = g_s[SC_OFF + 7] / ((float)(eend - b) + FEPS);
    float t = elu1(acc + g_s[H2_OFF + (size_t)d * NC + c] * perm);
    float mx = t;
#pragma unroll
    for (int o = 8; o; o >>= 1) mx = fmaxf(mx, __shfl_xor_sync(0xffffffffu, mx, o));
    float s2 = expf(t - mx);
#pragma unroll
    for (int o = 8; o; o >>= 1) s2 += __shfl_xor_sync(0xffffffffu, s2, o);
    float lse = mx + logf(s2);
    if (lane < 16) out[(size_t)d * NC + c] = t - lse;
}

// ---------------- launch ----------------
extern "C" void kernel_launch(void* const* d_in, const int* in_sizes, int n_in,
                              void* d_out, int out_size){
    const int*   src    = (const int*)  d_in[0];
    const int*   dst    = (const int*)  d_in[1];
    const float* x      = (const float*)d_in[2];
    const float* weights= (const float*)d_in[3];
    const float* latp   = (const float*)d_in[4];
    const float* sl_w   = (const float*)d_in[5];
    const float* sl_b   = (const float*)d_in[6];
    const float* slo_w  = (const float*)d_in[7];
    const float* slo_b  = (const float*)d_in[8];
    const float* fc1_w  = (const float*)d_in[9];
    const float* w_u1   = (const float*)d_in[10];
    const float* w_v1   = (const float*)d_in[11];
    const float* w_s1   = (const float*)d_in[12];
    const float* beta1  = (const float*)d_in[13];
    const float* aw1    = (const float*)d_in[14];
    const float* theta1 = (const float*)d_in[15];
    const float* fc2_w  = (const float*)d_in[16];
    const float* w_u2   = (const float*)d_in[17];
    const float* w_v2   = (const float*)d_in[18];
    const float* w_s2   = (const float*)d_in[19];
    const float* beta2  = (const float*)d_in[20];
    const float* aw2    = (const float*)d_in[21];
    const float* theta2 = (const float*)d_in[22];
    float* out = (float*)d_out;

    // k_gemm1 at launch index 3 so ncu's fixed sample slot captures it.
    k_zero<<<1024, 256>>>(beta1, aw1, theta1, beta2, aw2, theta2);
    k_indeg<<<(EE + 255) / 256, 256>>>(dst);
    k_scanA<<<NBLK, 256>>>();
    k_gemm1<<<(NN + 127) / 128, 256>>>(x, fc1_w, w_u1, w_v1);
    k_scanB<<<NBLK, 256>>>();
    k_scatter<<<(EE + 255) / 256, 256>>>(src, dst);
    k_dense2x<<<(NN * NC + 255) / 256, 256>>>(latp, sl_w, sl_b, slo_w, slo_b);
    k_edge1<<<(EE * 8 + 255) / 256, 256>>>(w_s1);
    k_agg1<<<(NN * 32 + 255) / 256, 256>>>();
    k_gemm2n<<<NN / 16, 256>>>(fc2_w, w_u2, w_v2);
    k_edge2<<<(EE + 255) / 256, 256>>>(w_s2, weights);
    k_agg2_final<<<(NN * 32 + 255) / 256, 256>>>(out, out_size);
}